// round 2
// baseline (speedup 1.0000x reference)
#include <cuda_runtime.h>
#include <cstdint>

#define NN 8192
#define IN_F 128
#define OUT_F 64
#define ALPHA 0.2f
#define NEG_BIG -9000000000000000.0f

#define TI 64
#define TJ 64
#define PT_STRIDE 68   // 64 + 4 pad: keeps float4 alignment (mult of 4) and kills bank conflicts

// Scratch (no allocations allowed in kernel_launch)
__device__ float g_Wh[NN * OUT_F];
__device__ float g_s1[NN];
__device__ float g_s2[NN];

// ---------- packed f32x2 helpers (sm_100+/sm_103a only) ----------
typedef unsigned long long u64p;

__device__ __forceinline__ u64p fpack2(float lo, float hi) {
    u64p d;
    asm("mov.b64 %0, {%1, %2};" : "=l"(d) : "f"(lo), "f"(hi));
    return d;
}
__device__ __forceinline__ void funpack2(u64p d, float& lo, float& hi) {
    asm("mov.b64 {%0, %1}, %2;" : "=f"(lo), "=f"(hi) : "l"(d));
}
__device__ __forceinline__ void ffma2(u64p& d, u64p a, u64p b) {
    asm("fma.rn.f32x2 %0, %1, %2, %3;" : "=l"(d) : "l"(a), "l"(b), "l"(d));
}
__device__ __forceinline__ u64p fmul2(u64p a, u64p b) {
    u64p d;
    asm("mul.rn.f32x2 %0, %1, %2;" : "=l"(d) : "l"(a), "l"(b));
    return d;
}

// ---------------------------------------------------------------------------
// Kernel 1: Wh = h @ W  (8192x128 @ 128x64), s1 = Wh@a1, s2 = Wh@a2
// block = 256 threads = 4 groups of 64; each group computes one row.
// ---------------------------------------------------------------------------
__global__ __launch_bounds__(256) void wh_kernel(const float* __restrict__ h,
                                                 const float* __restrict__ W,
                                                 const float* __restrict__ a) {
    __shared__ float W_s[IN_F * OUT_F];   // 32 KB
    __shared__ float h_s[4][IN_F];
    __shared__ float a_s[2 * OUT_F];
    __shared__ float red1[8], red2[8];

    const int t = threadIdx.x;
    const int rowBase = blockIdx.x * 4;

    for (int i = t; i < IN_F * OUT_F; i += 256) W_s[i] = W[i];
    if (t < 2 * OUT_F) a_s[t] = a[t];
    for (int i = t; i < 4 * IN_F; i += 256)
        h_s[i >> 7][i & 127] = h[(size_t)(rowBase + (i >> 7)) * IN_F + (i & 127)];
    __syncthreads();

    const int g = t >> 6;    // row within block
    const int c = t & 63;    // output column
    const int row = rowBase + g;

    float acc = 0.f;
#pragma unroll 8
    for (int k = 0; k < IN_F; ++k)
        acc += h_s[g][k] * W_s[k * OUT_F + c];

    g_Wh[row * OUT_F + c] = acc;

    float v1 = acc * a_s[c];
    float v2 = acc * a_s[OUT_F + c];
#pragma unroll
    for (int off = 16; off > 0; off >>= 1) {
        v1 += __shfl_down_sync(0xffffffffu, v1, off);
        v2 += __shfl_down_sync(0xffffffffu, v2, off);
    }
    if ((t & 31) == 0) { red1[t >> 5] = v1; red2[t >> 5] = v2; }
    __syncthreads();
    if (t < 4) {
        g_s1[rowBase + t] = red1[2 * t] + red1[2 * t + 1];
        g_s2[rowBase + t] = red2[2 * t] + red2[2 * t + 1];
    }
}

// ---------------------------------------------------------------------------
// Kernel 2: fused masked-softmax attention, flash style.
// grid = 128 blocks (64 rows each), 256 threads.
// Each thread owns a 4x4 output micro-tile (rows r0..r0+3, cols c0..c0+3),
// stored as 8 packed f32x2 accumulators (row pairs in lo/hi).
// ---------------------------------------------------------------------------
__global__ __launch_bounds__(256) void attn_kernel(const int* __restrict__ adj,
                                                   float* __restrict__ out) {
    __shared__ __align__(16) float pT_s[TJ * PT_STRIDE];  // transposed score/prob tile
    __shared__ __align__(16) float wh_s[TJ * OUT_F];      // Wh j-tile, row-major
    __shared__ float s1_s[TI], s2_s[TJ];
    __shared__ float m_s[TI], l_s[TI], scale_s[TI];

    const int t = threadIdx.x;
    const int iBase = blockIdx.x * TI;

    if (t < TI) {
        s1_s[t] = g_s1[iBase + t];
        m_s[t] = NEG_BIG;
        l_s[t] = 0.f;
    }

    const int thr_r = t >> 4;          // 0..15
    const int thr_c = t & 15;          // 0..15
    const int r0 = thr_r * 4;
    const int c0 = thr_c * 4;

    u64p acc2[2][4];                   // [row-pair][col], each = 2 packed rows
#pragma unroll
    for (int q = 0; q < 2; ++q)
#pragma unroll
        for (int cc = 0; cc < 4; ++cc) acc2[q][cc] = 0ull;

    const size_t adjBase = (size_t)iBase * NN;

    for (int jBase = 0; jBase < NN; jBase += TJ) {
        __syncthreads();  // protect smem tiles from previous iteration's readers

        if (t < TJ) s2_s[t] = g_s2[jBase + t];

        // load Wh j-tile (coalesced)
#pragma unroll
        for (int it = 0; it < 16; ++it) {
            int idx = it * 256 + t;
            wh_s[idx] = g_Wh[jBase * OUT_F + idx];
        }

        // s2_s produced by threads 0..63, consumed by ALL threads below.
        // (This missing barrier was the round-1 rel_err=1.3e-2 bug.)
        __syncthreads();

        // scores: e = mask(leakyrelu(s1+s2)), stored transposed
        const int* __restrict__ adjTile = adj + adjBase + jBase;
#pragma unroll
        for (int it = 0; it < 16; ++it) {
            int idx = it * 256 + t;
            int r = idx >> 6, jj = idx & 63;
            int av = __ldg(&adjTile[(size_t)r * NN + jj]);
            float e = s1_s[r] + s2_s[jj];
            e = (e >= 0.f) ? e : ALPHA * e;
            e = (av > 0) ? e : NEG_BIG;
            pT_s[jj * PT_STRIDE + r] = e;
        }
        __syncthreads();

        // online-softmax row pass: tile max -> new running max + rescale factor
        if (t < TI) {
            float tm = NEG_BIG;
#pragma unroll 8
            for (int jj = 0; jj < TJ; ++jj) tm = fmaxf(tm, pT_s[jj * PT_STRIDE + t]);
            float m_old = m_s[t];
            float m_new = fmaxf(m_old, tm);
            scale_s[t] = __expf(m_old - m_new);
            m_s[t] = m_new;
        }
        __syncthreads();

        // exponentiate in place
#pragma unroll
        for (int it = 0; it < 16; ++it) {
            int idx = it * 256 + t;
            int r = idx >> 6, jj = idx & 63;
            float e = pT_s[jj * PT_STRIDE + r];
            pT_s[jj * PT_STRIDE + r] = __expf(e - m_s[r]);
        }
        __syncthreads();

        // rescale accumulators; row threads also fold the tile row-sum into l
        {
            u64p scp0 = fpack2(scale_s[r0],     scale_s[r0 + 1]);
            u64p scp1 = fpack2(scale_s[r0 + 2], scale_s[r0 + 3]);
#pragma unroll
            for (int cc = 0; cc < 4; ++cc) {
                acc2[0][cc] = fmul2(acc2[0][cc], scp0);
                acc2[1][cc] = fmul2(acc2[1][cc], scp1);
            }
        }
        if (t < TI) {
            float sum = 0.f;
#pragma unroll 8
            for (int jj = 0; jj < TJ; ++jj) sum += pT_s[jj * PT_STRIDE + t];
            l_s[t] = l_s[t] * scale_s[t] + sum;
        }

        // P @ Wh micro-GEMM (packed f32x2: 16 FMA lanes per 8 FFMA2)
#pragma unroll 4
        for (int jj = 0; jj < TJ; ++jj) {
            ulonglong2 pd = *(const ulonglong2*)&pT_s[jj * PT_STRIDE + r0];  // rows r0..r0+3
            float4 wf = *(const float4*)&wh_s[(jj << 6) + c0];               // cols c0..c0+3
            u64p w0 = fpack2(wf.x, wf.x);
            u64p w1 = fpack2(wf.y, wf.y);
            u64p w2 = fpack2(wf.z, wf.z);
            u64p w3 = fpack2(wf.w, wf.w);
            ffma2(acc2[0][0], pd.x, w0); ffma2(acc2[1][0], pd.y, w0);
            ffma2(acc2[0][1], pd.x, w1); ffma2(acc2[1][1], pd.y, w1);
            ffma2(acc2[0][2], pd.x, w2); ffma2(acc2[1][2], pd.y, w2);
            ffma2(acc2[0][3], pd.x, w3); ffma2(acc2[1][3], pd.y, w3);
        }
    }
    __syncthreads();  // l_s final

    float linv[4];
#pragma unroll
    for (int rr = 0; rr < 4; ++rr) linv[rr] = 1.f / l_s[r0 + rr];

#pragma unroll
    for (int q = 0; q < 2; ++q) {
#pragma unroll
        for (int cc = 0; cc < 4; ++cc) {
            float x0, x1;
            funpack2(acc2[q][cc], x0, x1);
            x0 *= linv[2 * q];
            x1 *= linv[2 * q + 1];
            x0 = (x0 > 0.f) ? x0 : expm1f(x0);
            x1 = (x1 > 0.f) ? x1 : expm1f(x1);
            int row0 = iBase + r0 + 2 * q;
            out[(size_t)row0 * OUT_F + c0 + cc] = x0;
            out[(size_t)(row0 + 1) * OUT_F + c0 + cc] = x1;
        }
    }
}

// ---------------------------------------------------------------------------
extern "C" void kernel_launch(void* const* d_in, const int* in_sizes, int n_in,
                              void* d_out, int out_size) {
    const float* h   = (const float*)d_in[0];   // 8192 x 128
    const int*   adj = (const int*)d_in[1];     // 8192 x 8192
    const float* W   = (const float*)d_in[2];   // 128 x 64
    const float* a   = (const float*)d_in[3];   // 128 x 1
    float* out = (float*)d_out;                 // 8192 x 64

    wh_kernel<<<NN / 4, 256>>>(h, W, a);
    attn_kernel<<<NN / TI, 256>>>(adj, out);
}

// round 3
// speedup vs baseline: 2.0119x; 2.0119x over previous
#include <cuda_runtime.h>
#include <cstdint>

#define NN 8192
#define IN_F 128
#define OUT_F 64
#define ALPHA 0.2f
#define NEG_BIG -9000000000000000.0f

#define TI 64
#define TJ 64
#define PT_STRIDE 68   // 64 + 4 pad: float4-aligned, conflict-free columns
#define SPLITS 8
#define JSPAN (NN / SPLITS)          // 1024 columns per split
#define NTILE (NN / TI)              // 128 i-tiles

// Scratch (no allocations allowed anywhere)
__device__ float g_Wh[NN * OUT_F];
__device__ float g_s1[NN];
__device__ float g_s2[NN];
__device__ float g_accP[SPLITS][NN][OUT_F];   // 16 MB partial numerators
__device__ float g_mP[SPLITS][NN];
__device__ float g_lP[SPLITS][NN];

// ---------- packed f32x2 helpers (sm_100+/sm_103a only) ----------
typedef unsigned long long u64p;

__device__ __forceinline__ u64p fpack2(float lo, float hi) {
    u64p d;
    asm("mov.b64 %0, {%1, %2};" : "=l"(d) : "f"(lo), "f"(hi));
    return d;
}
__device__ __forceinline__ void funpack2(u64p d, float& lo, float& hi) {
    asm("mov.b64 {%0, %1}, %2;" : "=f"(lo), "=f"(hi) : "l"(d));
}
__device__ __forceinline__ void ffma2(u64p& d, u64p a, u64p b) {
    asm("fma.rn.f32x2 %0, %1, %2, %3;" : "=l"(d) : "l"(a), "l"(b), "l"(d));
}
__device__ __forceinline__ u64p fmul2(u64p a, u64p b) {
    u64p d;
    asm("mul.rn.f32x2 %0, %1, %2;" : "=l"(d) : "l"(a), "l"(b));
    return d;
}

// ---------------------------------------------------------------------------
// Kernel 1: Wh = h @ W, s1 = Wh@a1, s2 = Wh@a2
// ---------------------------------------------------------------------------
__global__ __launch_bounds__(256) void wh_kernel(const float* __restrict__ h,
                                                 const float* __restrict__ W,
                                                 const float* __restrict__ a) {
    __shared__ float W_s[IN_F * OUT_F];
    __shared__ float h_s[4][IN_F];
    __shared__ float a_s[2 * OUT_F];
    __shared__ float red1[8], red2[8];

    const int t = threadIdx.x;
    const int rowBase = blockIdx.x * 4;

    for (int i = t; i < IN_F * OUT_F; i += 256) W_s[i] = W[i];
    if (t < 2 * OUT_F) a_s[t] = a[t];
    for (int i = t; i < 4 * IN_F; i += 256)
        h_s[i >> 7][i & 127] = h[(size_t)(rowBase + (i >> 7)) * IN_F + (i & 127)];
    __syncthreads();

    const int g = t >> 6;
    const int c = t & 63;
    const int row = rowBase + g;

    float acc = 0.f;
#pragma unroll 8
    for (int k = 0; k < IN_F; ++k)
        acc += h_s[g][k] * W_s[k * OUT_F + c];

    g_Wh[row * OUT_F + c] = acc;

    float v1 = acc * a_s[c];
    float v2 = acc * a_s[OUT_F + c];
#pragma unroll
    for (int off = 16; off > 0; off >>= 1) {
        v1 += __shfl_down_sync(0xffffffffu, v1, off);
        v2 += __shfl_down_sync(0xffffffffu, v2, off);
    }
    if ((t & 31) == 0) { red1[t >> 5] = v1; red2[t >> 5] = v2; }
    __syncthreads();
    if (t < 4) {
        g_s1[rowBase + t] = red1[2 * t] + red1[2 * t + 1];
        g_s2[rowBase + t] = red2[2 * t] + red2[2 * t + 1];
    }
}

// ---------------------------------------------------------------------------
// Kernel 2: split-j flash attention. grid = (128 i-tiles, 8 j-splits).
// Each CTA covers 64 rows x 1024 cols; writes partial (m, l, acc) to scratch.
// ---------------------------------------------------------------------------
__global__ __launch_bounds__(256) void attn_kernel(const int* __restrict__ adj) {
    __shared__ __align__(16) float pT_s[TJ * PT_STRIDE];
    __shared__ __align__(16) float wh_s[TJ * OUT_F];
    __shared__ float s1_s[TI], s2_s[TJ];
    __shared__ float m_s[TI], l_s[TI], scale_s[TI];

    const int t = threadIdx.x;
    const int iBase = blockIdx.x * TI;
    const int split = blockIdx.y;
    const int jStart = split * JSPAN;

    if (t < TI) {
        s1_s[t] = g_s1[iBase + t];
        m_s[t] = NEG_BIG;
        l_s[t] = 0.f;
    }

    const int r0 = (t >> 4) * 4;
    const int c0 = (t & 15) * 4;

    u64p acc2[2][4];
#pragma unroll
    for (int q = 0; q < 2; ++q)
#pragma unroll
        for (int cc = 0; cc < 4; ++cc) acc2[q][cc] = 0ull;

    const size_t adjBase = (size_t)iBase * NN;

    for (int jBase = jStart; jBase < jStart + JSPAN; jBase += TJ) {
        __syncthreads();  // protect tiles from previous iteration readers

        if (t < TJ) s2_s[t] = g_s2[jBase + t];

#pragma unroll
        for (int it = 0; it < 16; ++it) {
            int idx = it * 256 + t;
            wh_s[idx] = g_Wh[jBase * OUT_F + idx];
        }
        __syncthreads();  // s2_s / wh_s ready

        const int* __restrict__ adjTile = adj + adjBase + jBase;
#pragma unroll
        for (int it = 0; it < 16; ++it) {
            int idx = it * 256 + t;
            int r = idx >> 6, jj = idx & 63;
            int av = __ldg(&adjTile[(size_t)r * NN + jj]);
            float e = s1_s[r] + s2_s[jj];
            e = (e >= 0.f) ? e : ALPHA * e;
            e = (av > 0) ? e : NEG_BIG;
            pT_s[jj * PT_STRIDE + r] = e;
        }
        __syncthreads();

        if (t < TI) {
            float tm = NEG_BIG;
#pragma unroll 8
            for (int jj = 0; jj < TJ; ++jj) tm = fmaxf(tm, pT_s[jj * PT_STRIDE + t]);
            float m_old = m_s[t];
            float m_new = fmaxf(m_old, tm);
            scale_s[t] = __expf(m_old - m_new);
            m_s[t] = m_new;
        }
        __syncthreads();

#pragma unroll
        for (int it = 0; it < 16; ++it) {
            int idx = it * 256 + t;
            int r = idx >> 6, jj = idx & 63;
            float e = pT_s[jj * PT_STRIDE + r];
            pT_s[jj * PT_STRIDE + r] = __expf(e - m_s[r]);
        }
        __syncthreads();

        {
            u64p scp0 = fpack2(scale_s[r0],     scale_s[r0 + 1]);
            u64p scp1 = fpack2(scale_s[r0 + 2], scale_s[r0 + 3]);
#pragma unroll
            for (int cc = 0; cc < 4; ++cc) {
                acc2[0][cc] = fmul2(acc2[0][cc], scp0);
                acc2[1][cc] = fmul2(acc2[1][cc], scp1);
            }
        }
        if (t < TI) {
            float sum = 0.f;
#pragma unroll 8
            for (int jj = 0; jj < TJ; ++jj) sum += pT_s[jj * PT_STRIDE + t];
            l_s[t] = l_s[t] * scale_s[t] + sum;
        }

#pragma unroll 4
        for (int jj = 0; jj < TJ; ++jj) {
            ulonglong2 pd = *(const ulonglong2*)&pT_s[jj * PT_STRIDE + r0];
            float4 wf = *(const float4*)&wh_s[(jj << 6) + c0];
            u64p w0 = fpack2(wf.x, wf.x);
            u64p w1 = fpack2(wf.y, wf.y);
            u64p w2 = fpack2(wf.z, wf.z);
            u64p w3 = fpack2(wf.w, wf.w);
            ffma2(acc2[0][0], pd.x, w0); ffma2(acc2[1][0], pd.y, w0);
            ffma2(acc2[0][1], pd.x, w1); ffma2(acc2[1][1], pd.y, w1);
            ffma2(acc2[0][2], pd.x, w2); ffma2(acc2[1][2], pd.y, w2);
            ffma2(acc2[0][3], pd.x, w3); ffma2(acc2[1][3], pd.y, w3);
        }
    }
    __syncthreads();  // l_s / m_s final

    if (t < TI) {
        g_mP[split][iBase + t] = m_s[t];
        g_lP[split][iBase + t] = l_s[t];
    }

#pragma unroll
    for (int q = 0; q < 2; ++q) {
#pragma unroll
        for (int cc = 0; cc < 4; ++cc) {
            float x0, x1;
            funpack2(acc2[q][cc], x0, x1);
            int row0 = iBase + r0 + 2 * q;
            g_accP[split][row0][c0 + cc] = x0;
            g_accP[split][row0 + 1][c0 + cc] = x1;
        }
    }
}

// ---------------------------------------------------------------------------
// Kernel 3: combine split partials -> softmax-normalized output + ELU.
// grid = 512 blocks x 16 rows.
// ---------------------------------------------------------------------------
__global__ __launch_bounds__(256) void combine_kernel(float* __restrict__ out) {
    __shared__ float w_s[SPLITS][16];
    __shared__ float linv_s[16];

    const int t = threadIdx.x;
    const int rowBase = blockIdx.x * 16;

    if (t < 16) {
        int row = rowBase + t;
        float m = NEG_BIG;
#pragma unroll
        for (int s = 0; s < SPLITS; ++s) m = fmaxf(m, g_mP[s][row]);
        float L = 0.f;
#pragma unroll
        for (int s = 0; s < SPLITS; ++s) {
            float w = __expf(g_mP[s][row] - m);
            w_s[s][t] = w;
            L += g_lP[s][row] * w;
        }
        linv_s[t] = 1.f / L;
    }
    __syncthreads();

#pragma unroll
    for (int it = 0; it < 4; ++it) {
        int idx = it * 256 + t;
        int r = idx >> 6, c = idx & 63;
        int row = rowBase + r;
        float acc = 0.f;
#pragma unroll
        for (int s = 0; s < SPLITS; ++s)
            acc += g_accP[s][row][c] * w_s[s][r];
        float x = acc * linv_s[r];
        x = (x > 0.f) ? x : expm1f(x);
        out[(size_t)row * OUT_F + c] = x;
    }
}

// ---------------------------------------------------------------------------
extern "C" void kernel_launch(void* const* d_in, const int* in_sizes, int n_in,
                              void* d_out, int out_size) {
    const float* h   = (const float*)d_in[0];   // 8192 x 128
    const int*   adj = (const int*)d_in[1];     // 8192 x 8192
    const float* W   = (const float*)d_in[2];   // 128 x 64
    const float* a   = (const float*)d_in[3];   // 128 x 1
    float* out = (float*)d_out;                 // 8192 x 64

    wh_kernel<<<NN / 4, 256>>>(h, W, a);
    attn_kernel<<<dim3(NTILE, SPLITS), 256>>>(adj);
    combine_kernel<<<NN / 16, 256>>>(out);
}

// round 4
// speedup vs baseline: 2.7380x; 1.3609x over previous
#include <cuda_runtime.h>
#include <cstdint>

#define NN 8192
#define IN_F 128
#define OUT_F 64
#define ALPHA 0.2f
#define NEG_BIG -9000000000000000.0f

#define TI 64
#define TJ 64
#define PT_STRIDE 68   // 64+4 pad; 68*4 bytes = multiple of 16 -> float4-aligned columns
#define SPLITS 8
#define JSPAN (NN / SPLITS)
#define NTILE (NN / TI)

// Scratch (no allocations allowed anywhere)
__device__ float g_Wh[NN * OUT_F];
__device__ float g_s1[NN];
__device__ float g_s2[NN];
__device__ float g_accP[SPLITS][NN][OUT_F];   // 16 MB partial numerators
__device__ float g_lP[SPLITS][NN];            // partial denominators

// ---------- packed f32x2 helpers (sm_100+/sm_103a only) ----------
typedef unsigned long long u64p;

__device__ __forceinline__ u64p fpack2(float lo, float hi) {
    u64p d;
    asm("mov.b64 %0, {%1, %2};" : "=l"(d) : "f"(lo), "f"(hi));
    return d;
}
__device__ __forceinline__ void funpack2(u64p d, float& lo, float& hi) {
    asm("mov.b64 {%0, %1}, %2;" : "=f"(lo), "=f"(hi) : "l"(d));
}
__device__ __forceinline__ void ffma2(u64p& d, u64p a, u64p b) {
    asm("fma.rn.f32x2 %0, %1, %2, %3;" : "=l"(d) : "l"(a), "l"(b), "l"(d));
}
__device__ __forceinline__ void fadd2(u64p& d, u64p a) {
    asm("add.rn.f32x2 %0, %1, %2;" : "=l"(d) : "l"(d), "l"(a));
}

// ---------------------------------------------------------------------------
// Kernel 1: Wh = h @ W, s1 = Wh@a1, s2 = Wh@a2.
// 16 rows per block (4 row-groups reusing W_s) to cut W read amplification.
// ---------------------------------------------------------------------------
__global__ __launch_bounds__(256) void wh_kernel(const float* __restrict__ h,
                                                 const float* __restrict__ W,
                                                 const float* __restrict__ a) {
    __shared__ float W_s[IN_F * OUT_F];   // 32 KB
    __shared__ float h_s[4][IN_F];
    __shared__ float a_s[2 * OUT_F];
    __shared__ float red1[8], red2[8];

    const int t = threadIdx.x;
    const int blockRow = blockIdx.x * 16;

    for (int i = t; i < IN_F * OUT_F; i += 256) W_s[i] = W[i];
    if (t < 2 * OUT_F) a_s[t] = a[t];

    const int g = t >> 6;    // row within group
    const int c = t & 63;    // output column

    for (int rg = 0; rg < 4; ++rg) {
        const int rowBase = blockRow + rg * 4;
        __syncthreads();   // previous h_s readers done (and W_s ready on rg=0)
        for (int i = t; i < 4 * IN_F; i += 256)
            h_s[i >> 7][i & 127] = h[(size_t)(rowBase + (i >> 7)) * IN_F + (i & 127)];
        __syncthreads();

        const int row = rowBase + g;
        float acc = 0.f;
#pragma unroll 8
        for (int k = 0; k < IN_F; ++k)
            acc += h_s[g][k] * W_s[k * OUT_F + c];

        g_Wh[row * OUT_F + c] = acc;

        float v1 = acc * a_s[c];
        float v2 = acc * a_s[OUT_F + c];
#pragma unroll
        for (int off = 16; off > 0; off >>= 1) {
            v1 += __shfl_down_sync(0xffffffffu, v1, off);
            v2 += __shfl_down_sync(0xffffffffu, v2, off);
        }
        if ((t & 31) == 0) { red1[t >> 5] = v1; red2[t >> 5] = v2; }
        __syncthreads();
        if (t < 4) {
            g_s1[rowBase + t] = red1[2 * t] + red1[2 * t + 1];
            g_s2[rowBase + t] = red2[2 * t] + red2[2 * t + 1];
        }
    }
}

// ---------------------------------------------------------------------------
// Kernel 2: split-j attention, NO online softmax (scores are bounded, direct
// exp is exact in fp32; masked entries are literal 0).
// grid = (128 i-tiles, 8 j-splits), 256 threads, 2 barriers per j-tile.
// Each thread: 4x4 output micro-tile as packed f32x2 accumulators.
// ---------------------------------------------------------------------------
__global__ void __launch_bounds__(256, 4) attn_kernel(const int* __restrict__ adj) {
    __shared__ __align__(16) float pT_s[TJ * PT_STRIDE];  // transposed prob tile
    __shared__ __align__(16) float wh_s[TJ * OUT_F];      // Wh j-tile, row-major
    __shared__ float s1_s[TI];

    const int t = threadIdx.x;
    const int iBase = blockIdx.x * TI;
    const int split = blockIdx.y;
    const int jStart = split * JSPAN;

    if (t < TI) s1_s[t] = g_s1[iBase + t];

    const int r0 = (t >> 4) * 4;
    const int c0 = (t & 15) * 4;
    const bool sumThread = ((t & 15) == 0);

    u64p acc2[2][4];
#pragma unroll
    for (int q = 0; q < 2; ++q)
#pragma unroll
        for (int cc = 0; cc < 4; ++cc) acc2[q][cc] = 0ull;
    u64p lsum0 = 0ull, lsum1 = 0ull;

    const size_t adjBase = (size_t)iBase * NN;
    __syncthreads();   // s1_s ready

    for (int jBase = jStart; jBase < jStart + JSPAN; jBase += TJ) {
        // ---- score pass: p = exp(mask(leakyrelu(s1+s2))), transposed store
        const int4* __restrict__ adjT = (const int4*)(adj + adjBase + jBase);
#pragma unroll
        for (int it = 0; it < 4; ++it) {
            int idx4 = it * 256 + t;          // 0..1023
            int r = idx4 >> 4;                // 16 int4 per 64-col row
            int q = idx4 & 15;
            int jj = q * 4;
            int4 av = __ldg(&adjT[(size_t)r * (NN / 4) + q]);
            float4 s2v = *(const float4*)&g_s2[jBase + jj];
            float s1r = s1_s[r];
            float e0 = s1r + s2v.x; e0 = (e0 >= 0.f) ? e0 : ALPHA * e0;
            float e1 = s1r + s2v.y; e1 = (e1 >= 0.f) ? e1 : ALPHA * e1;
            float e2 = s1r + s2v.z; e2 = (e2 >= 0.f) ? e2 : ALPHA * e2;
            float e3 = s1r + s2v.w; e3 = (e3 >= 0.f) ? e3 : ALPHA * e3;
            float p0 = (av.x > 0) ? __expf(e0) : 0.f;
            float p1 = (av.y > 0) ? __expf(e1) : 0.f;
            float p2 = (av.z > 0) ? __expf(e2) : 0.f;
            float p3 = (av.w > 0) ? __expf(e3) : 0.f;
            pT_s[(jj + 0) * PT_STRIDE + r] = p0;
            pT_s[(jj + 1) * PT_STRIDE + r] = p1;
            pT_s[(jj + 2) * PT_STRIDE + r] = p2;
            pT_s[(jj + 3) * PT_STRIDE + r] = p3;
        }

        // ---- Wh j-tile load (overlaps adj latency)
        {
            const float4* src = (const float4*)(g_Wh + jBase * OUT_F);
            float4* dst = (float4*)wh_s;
#pragma unroll
            for (int it = 0; it < 4; ++it)
                dst[it * 256 + t] = src[it * 256 + t];
        }
        __syncthreads();   // pT_s + wh_s ready

        // ---- micro-GEMM P @ Wh, with row sums folded into one thread column
#pragma unroll 4
        for (int jj = 0; jj < TJ; ++jj) {
            ulonglong2 pd = *(const ulonglong2*)&pT_s[jj * PT_STRIDE + r0];
            float4 wf = *(const float4*)&wh_s[(jj << 6) + c0];
            u64p w0 = fpack2(wf.x, wf.x);
            u64p w1 = fpack2(wf.y, wf.y);
            u64p w2 = fpack2(wf.z, wf.z);
            u64p w3 = fpack2(wf.w, wf.w);
            ffma2(acc2[0][0], pd.x, w0); ffma2(acc2[1][0], pd.y, w0);
            ffma2(acc2[0][1], pd.x, w1); ffma2(acc2[1][1], pd.y, w1);
            ffma2(acc2[0][2], pd.x, w2); ffma2(acc2[1][2], pd.y, w2);
            ffma2(acc2[0][3], pd.x, w3); ffma2(acc2[1][3], pd.y, w3);
            if (sumThread) { fadd2(lsum0, pd.x); fadd2(lsum1, pd.y); }
        }
        __syncthreads();   // GEMM done before next tile overwrites pT_s/wh_s
    }

    // ---- write partials
    if (sumThread) {
        float a0, a1, b0, b1;
        funpack2(lsum0, a0, a1);
        funpack2(lsum1, b0, b1);
        g_lP[split][iBase + r0 + 0] = a0;
        g_lP[split][iBase + r0 + 1] = a1;
        g_lP[split][iBase + r0 + 2] = b0;
        g_lP[split][iBase + r0 + 3] = b1;
    }

#pragma unroll
    for (int q = 0; q < 2; ++q) {
#pragma unroll
        for (int cc = 0; cc < 4; ++cc) {
            float x0, x1;
            funpack2(acc2[q][cc], x0, x1);
            int row0 = iBase + r0 + 2 * q;
            g_accP[split][row0][c0 + cc] = x0;
            g_accP[split][row0 + 1][c0 + cc] = x1;
        }
    }
}

// ---------------------------------------------------------------------------
// Kernel 3: plain sum of split partials -> normalize -> ELU.
// grid = 512 blocks x 16 rows; one float4 per thread.
// ---------------------------------------------------------------------------
__global__ __launch_bounds__(256) void combine_kernel(float* __restrict__ out) {
    __shared__ float linv_s[16];

    const int t = threadIdx.x;
    const int rowBase = blockIdx.x * 16;

    if (t < 16) {
        int row = rowBase + t;
        float L = 0.f;
#pragma unroll
        for (int s = 0; s < SPLITS; ++s) L += g_lP[s][row];
        linv_s[t] = 1.f / L;
    }
    __syncthreads();

    const int r = t >> 4;          // 0..15
    const int c4 = (t & 15);       // float4 column index
    const int row = rowBase + r;

    float4 acc = make_float4(0.f, 0.f, 0.f, 0.f);
#pragma unroll
    for (int s = 0; s < SPLITS; ++s) {
        float4 v = *(const float4*)&g_accP[s][row][c4 * 4];
        acc.x += v.x; acc.y += v.y; acc.z += v.z; acc.w += v.w;
    }
    float li = linv_s[r];
    float x0 = acc.x * li, x1 = acc.y * li, x2 = acc.z * li, x3 = acc.w * li;
    x0 = (x0 > 0.f) ? x0 : expm1f(x0);
    x1 = (x1 > 0.f) ? x1 : expm1f(x1);
    x2 = (x2 > 0.f) ? x2 : expm1f(x2);
    x3 = (x3 > 0.f) ? x3 : expm1f(x3);
    float4 o = make_float4(x0, x1, x2, x3);
    *(float4*)&out[(size_t)row * OUT_F + c4 * 4] = o;
}

// ---------------------------------------------------------------------------
extern "C" void kernel_launch(void* const* d_in, const int* in_sizes, int n_in,
                              void* d_out, int out_size) {
    const float* h   = (const float*)d_in[0];   // 8192 x 128
    const int*   adj = (const int*)d_in[1];     // 8192 x 8192
    const float* W   = (const float*)d_in[2];   // 128 x 64
    const float* a   = (const float*)d_in[3];   // 128 x 1
    float* out = (float*)d_out;                 // 8192 x 64

    wh_kernel<<<NN / 16, 256>>>(h, W, a);
    attn_kernel<<<dim3(NTILE, SPLITS), 256>>>(adj);
    combine_kernel<<<NN / 16, 256>>>(out);
}

// round 6
// speedup vs baseline: 5.6279x; 2.0555x over previous
#include <cuda_runtime.h>
#include <cuda_bf16.h>
#include <cstdint>

#define NN 8192
#define IN_F 128
#define OUT_F 64
#define ALPHA 0.2f

#define TI 128                 // CTA row tile
#define BK 128                 // j per B stage
#define SPLITS 8
#define JSPAN (NN / SPLITS)    // 1024
#define NTI (NN / TI)          // 64

#define BSTRIDE 272            // bytes per n-row in B stage (128*2 + 16 pad) -> conflict-free
#define BHALF 17408            // 64 * 272

// Scratch
__device__ float g_s1[NN];
__device__ float g_s2[NN];
__device__ __nv_bfloat16 g_WhT_hi[OUT_F * NN];   // transposed Wh, bf16 hi
__device__ __nv_bfloat16 g_WhT_lo[OUT_F * NN];   // bf16 residual
__device__ float g_accP[SPLITS][NN][OUT_F];
__device__ float g_lP[SPLITS][NN];

// pack two fp32 -> {low16=bf16(x0), high16=bf16(x1)} by truncation
__device__ __forceinline__ uint32_t pack_bf16(float x0, float x1) {
    return __byte_perm(__float_as_uint(x0), __float_as_uint(x1), 0x7632);
}
__device__ __forceinline__ float bf16_trunc_f(float x) {
    return __uint_as_float(__float_as_uint(x) & 0xFFFF0000u);
}

__device__ __forceinline__ void mma16816(float* d,
                                         uint32_t a0, uint32_t a1, uint32_t a2, uint32_t a3,
                                         uint32_t b0, uint32_t b1) {
    asm volatile(
        "mma.sync.aligned.m16n8k16.row.col.f32.bf16.bf16.f32 "
        "{%0,%1,%2,%3}, {%4,%5,%6,%7}, {%8,%9}, {%0,%1,%2,%3};"
        : "+f"(d[0]), "+f"(d[1]), "+f"(d[2]), "+f"(d[3])
        : "r"(a0), "r"(a1), "r"(a2), "r"(a3), "r"(b0), "r"(b1));
}

// ---------------------------------------------------------------------------
// Kernel 1: Wh = h@W; s1 = Wh@a1; s2 = Wh@a2; WhT hi/lo bf16 split.
// ---------------------------------------------------------------------------
__global__ __launch_bounds__(256) void wh_kernel(const float* __restrict__ h,
                                                 const float* __restrict__ W,
                                                 const float* __restrict__ a) {
    __shared__ float W_s[IN_F * OUT_F];
    __shared__ float h_s[4][IN_F];
    __shared__ float a_s[2 * OUT_F];
    __shared__ float red1[8], red2[8];
    __shared__ float tr[OUT_F][17];

    const int t = threadIdx.x;
    const int blockRow = blockIdx.x * 16;

    for (int i = t; i < IN_F * OUT_F; i += 256) W_s[i] = W[i];
    if (t < 2 * OUT_F) a_s[t] = a[t];

    const int g = t >> 6;
    const int c = t & 63;

    for (int rg = 0; rg < 4; ++rg) {
        const int rowBase = blockRow + rg * 4;
        __syncthreads();
        for (int i = t; i < 4 * IN_F; i += 256)
            h_s[i >> 7][i & 127] = h[(size_t)(rowBase + (i >> 7)) * IN_F + (i & 127)];
        __syncthreads();

        float acc = 0.f;
#pragma unroll 8
        for (int k = 0; k < IN_F; ++k)
            acc += h_s[g][k] * W_s[k * OUT_F + c];

        tr[c][rg * 4 + g] = acc;

        float v1 = acc * a_s[c];
        float v2 = acc * a_s[OUT_F + c];
#pragma unroll
        for (int off = 16; off > 0; off >>= 1) {
            v1 += __shfl_down_sync(0xffffffffu, v1, off);
            v2 += __shfl_down_sync(0xffffffffu, v2, off);
        }
        if ((t & 31) == 0) { red1[t >> 5] = v1; red2[t >> 5] = v2; }
        __syncthreads();
        if (t < 4) {
            g_s1[rowBase + t] = red1[2 * t] + red1[2 * t + 1];
            g_s2[rowBase + t] = red2[2 * t] + red2[2 * t + 1];
        }
    }
    __syncthreads();

    // transposed bf16 hi/lo write-out: thread t -> col cc=t>>2, rows q*4..+3
    {
        const int cc = t >> 2;
        const int q = t & 3;
        float v[4], hi[4], lo[4];
#pragma unroll
        for (int i = 0; i < 4; ++i) {
            v[i] = tr[cc][q * 4 + i];
            hi[i] = bf16_trunc_f(v[i]);
            lo[i] = v[i] - hi[i];
        }
        size_t o = (size_t)cc * NN + blockRow + q * 4;
        uint2 ph = make_uint2(pack_bf16(hi[0], hi[1]), pack_bf16(hi[2], hi[3]));
        uint2 pl = make_uint2(pack_bf16(lo[0], lo[1]), pack_bf16(lo[2], lo[3]));
        *(uint2*)&g_WhT_hi[o] = ph;
        *(uint2*)&g_WhT_lo[o] = pl;
    }
}

// ---------------------------------------------------------------------------
// Kernel 2: mma.sync bf16 attention, A (P) computed straight into fragment
// registers (no P SMEM). grid=(64 i-tiles, 8 splits), 256 threads (8 warps).
// Warp w: rows w*16..w*16+15; D = 16x64 per warp, fp32 accum in regs.
// ---------------------------------------------------------------------------
__global__ void __launch_bounds__(256) attn_kernel(const int* __restrict__ adj) {
    __shared__ __align__(16) unsigned char Bs[2 * BHALF];  // hi | lo, 64 rows x 272B
    __shared__ __align__(16) float s2_s[JSPAN];

    const int t = threadIdx.x;
    const int wid = t >> 5;
    const int lane = t & 31;
    const int qr = lane >> 2;      // 0..7
    const int qm = lane & 3;       // 0..3

    const int iBase = blockIdx.x * TI;
    const int split = blockIdx.y;
    const int jStart = split * JSPAN;

    const int r0 = wid * 16 + qr;      // local row for a0/a2
    const int r1 = r0 + 8;             // a1/a3
    const float s1r0 = g_s1[iBase + r0];
    const float s1r1 = g_s1[iBase + r1];
    const int* __restrict__ row0 = adj + (size_t)(iBase + r0) * NN;
    const int* __restrict__ row1 = adj + (size_t)(iBase + r1) * NN;

    // s2 span -> smem
    {
        const float4* src = (const float4*)&g_s2[jStart];
        ((float4*)s2_s)[t] = src[t];
    }

    float d[8][4];
#pragma unroll
    for (int nt = 0; nt < 8; ++nt)
#pragma unroll
        for (int i = 0; i < 4; ++i) d[nt][i] = 0.f;
    float lsum0 = 0.f, lsum1 = 0.f;

    const int nrow = wid * 2;   // B-stage cooperative load helper (unused granularity)

    for (int stage = 0; stage < JSPAN / BK; ++stage) {
        const int jStage = jStart + stage * BK;

        __syncthreads();   // prior MMAs done before overwriting Bs (also covers s2 on stage 0)

        // ---- load B stage: WhT hi/lo bf16, 64 n-rows x 128 k, padded stride
        for (int idx = t; idx < 2048; idx += 256) {
            int half = idx >> 10;          // 0 = hi, 1 = lo
            int rem = idx & 1023;
            int n = rem >> 4;              // 0..63
            int seg = rem & 15;            // 16B segment
            const __nv_bfloat16* gsrc = (half ? g_WhT_lo : g_WhT_hi) + (size_t)n * NN + jStage;
            uint4 v = ((const uint4*)gsrc)[seg];
            *(uint4*)(Bs + half * BHALF + n * BSTRIDE + seg * 16) = v;
        }
        __syncthreads();

        // ---- 8 chunks of 16 j
#pragma unroll 2
        for (int c = 0; c < 8; ++c) {
            const int jc = stage * BK + c * 16 + 2 * qm;   // local j (within span)
            const int gj = jStage + c * 16 + 2 * qm;       // global j

            int2 A0 = __ldg((const int2*)(row0 + gj));
            int2 A2 = __ldg((const int2*)(row0 + gj + 8));
            int2 A1 = __ldg((const int2*)(row1 + gj));
            int2 A3 = __ldg((const int2*)(row1 + gj + 8));
            float2 s2a = *(const float2*)&s2_s[jc];
            float2 s2b = *(const float2*)&s2_s[jc + 8];

            float e, p00, p01, p02, p03, p10, p11, p12, p13;
            e = s1r0 + s2a.x; e = fmaxf(e, ALPHA * e); p00 = (A0.x > 0) ? __expf(e) : 0.f;
            e = s1r0 + s2a.y; e = fmaxf(e, ALPHA * e); p01 = (A0.y > 0) ? __expf(e) : 0.f;
            e = s1r0 + s2b.x; e = fmaxf(e, ALPHA * e); p02 = (A2.x > 0) ? __expf(e) : 0.f;
            e = s1r0 + s2b.y; e = fmaxf(e, ALPHA * e); p03 = (A2.y > 0) ? __expf(e) : 0.f;
            e = s1r1 + s2a.x; e = fmaxf(e, ALPHA * e); p10 = (A1.x > 0) ? __expf(e) : 0.f;
            e = s1r1 + s2a.y; e = fmaxf(e, ALPHA * e); p11 = (A1.y > 0) ? __expf(e) : 0.f;
            e = s1r1 + s2b.x; e = fmaxf(e, ALPHA * e); p12 = (A3.x > 0) ? __expf(e) : 0.f;
            e = s1r1 + s2b.y; e = fmaxf(e, ALPHA * e); p13 = (A3.y > 0) ? __expf(e) : 0.f;

            lsum0 += (p00 + p01) + (p02 + p03);
            lsum1 += (p10 + p11) + (p12 + p13);

            // hi/lo fragment packing (truncation split)
            uint32_t a0h = pack_bf16(p00, p01), a2h = pack_bf16(p02, p03);
            uint32_t a1h = pack_bf16(p10, p11), a3h = pack_bf16(p12, p13);
            uint32_t a0l = pack_bf16(p00 - bf16_trunc_f(p00), p01 - bf16_trunc_f(p01));
            uint32_t a2l = pack_bf16(p02 - bf16_trunc_f(p02), p03 - bf16_trunc_f(p03));
            uint32_t a1l = pack_bf16(p10 - bf16_trunc_f(p10), p11 - bf16_trunc_f(p11));
            uint32_t a3l = pack_bf16(p12 - bf16_trunc_f(p12), p13 - bf16_trunc_f(p13));

            // base byte offset within a B n-row for this chunk + lane k
            const int kOff = c * 32 + qm * 4;
#pragma unroll
            for (int nt = 0; nt < 8; ++nt) {
                const unsigned char* bp = Bs + (nt * 8 + qr) * BSTRIDE + kOff;
                uint32_t bh0 = *(const uint32_t*)bp;
                uint32_t bh1 = *(const uint32_t*)(bp + 16);
                uint32_t bl0 = *(const uint32_t*)(bp + BHALF);
                uint32_t bl1 = *(const uint32_t*)(bp + BHALF + 16);
                mma16816(d[nt], a0h, a1h, a2h, a3h, bh0, bh1);
                mma16816(d[nt], a0h, a1h, a2h, a3h, bl0, bl1);
                mma16816(d[nt], a0l, a1l, a2l, a3l, bh0, bh1);
            }
        }
    }

    // ---- row sums: reduce across the 4 lanes of each quad-column group
    lsum0 += __shfl_xor_sync(0xffffffffu, lsum0, 1);
    lsum0 += __shfl_xor_sync(0xffffffffu, lsum0, 2);
    lsum1 += __shfl_xor_sync(0xffffffffu, lsum1, 1);
    lsum1 += __shfl_xor_sync(0xffffffffu, lsum1, 2);
    if (qm == 0) {
        g_lP[split][iBase + r0] = lsum0;
        g_lP[split][iBase + r1] = lsum1;
    }

    // ---- write partials: d[nt] = rows (r0, r1), cols nt*8 + 2*qm + {0,1}
    {
        float* base0 = &g_accP[split][iBase + r0][0];
        float* base1 = &g_accP[split][iBase + r1][0];
#pragma unroll
        for (int nt = 0; nt < 8; ++nt) {
            int cb = nt * 8 + 2 * qm;
            *(float2*)&base0[cb] = make_float2(d[nt][0], d[nt][1]);
            *(float2*)&base1[cb] = make_float2(d[nt][2], d[nt][3]);
        }
    }
    (void)nrow;
}

// ---------------------------------------------------------------------------
// Kernel 3: sum split partials -> normalize -> ELU.
// ---------------------------------------------------------------------------
__global__ __launch_bounds__(256) void combine_kernel(float* __restrict__ out) {
    __shared__ float linv_s[16];
    const int t = threadIdx.x;
    const int rowBase = blockIdx.x * 16;

    if (t < 16) {
        int row = rowBase + t;
        float L = 0.f;
#pragma unroll
        for (int s = 0; s < SPLITS; ++s) L += g_lP[s][row];
        linv_s[t] = 1.f / L;
    }
    __syncthreads();

    const int rr = t >> 4;
    const int c4 = t & 15;
    const int row = rowBase + rr;

    float4 acc = make_float4(0.f, 0.f, 0.f, 0.f);
#pragma unroll
    for (int s = 0; s < SPLITS; ++s) {
        float4 v = *(const float4*)&g_accP[s][row][c4 * 4];
        acc.x += v.x; acc.y += v.y; acc.z += v.z; acc.w += v.w;
    }
    float li = linv_s[rr];
    float x0 = acc.x * li, x1 = acc.y * li, x2 = acc.z * li, x3 = acc.w * li;
    x0 = (x0 > 0.f) ? x0 : expm1f(x0);
    x1 = (x1 > 0.f) ? x1 : expm1f(x1);
    x2 = (x2 > 0.f) ? x2 : expm1f(x2);
    x3 = (x3 > 0.f) ? x3 : expm1f(x3);
    *(float4*)&out[(size_t)row * OUT_F + c4 * 4] = make_float4(x0, x1, x2, x3);
}

// ---------------------------------------------------------------------------
extern "C" void kernel_launch(void* const* d_in, const int* in_sizes, int n_in,
                              void* d_out, int out_size) {
    const float* h   = (const float*)d_in[0];   // 8192 x 128
    const int*   adj = (const int*)d_in[1];     // 8192 x 8192
    const float* W   = (const float*)d_in[2];   // 128 x 64
    const float* a   = (const float*)d_in[3];   // 128 x 1
    float* out = (float*)d_out;                 // 8192 x 64

    wh_kernel<<<NN / 16, 256>>>(h, W, a);
    attn_kernel<<<dim3(NTI, SPLITS), 256>>>(adj);
    combine_kernel<<<NN / 16, 256>>>(out);
}